// round 16
// baseline (speedup 1.0000x reference)
#include <cuda_runtime.h>
#include <cuda_bf16.h>
#include <cstdint>

#define T_LEN 32768
#define HID   256
#define NI_   1024
#define OUT_  32
#define HSTR  1056   // padded h-buffer stride (bytes): half0 @0..512, half1 @528..1040
#define NCHK  18     // chunks per direction (2 per cluster, interleaved)
#define NPAIR 9      // chunk-pairs per direction = clusters per direction
#define CHKL  1821   // chunk length (18*1821 >= 32768)
#define WARM  256    // warmup steps (rho<0.95 proven => rho^256 < 2e-6)

// ---------------- scratch (device globals: no allocation allowed) ----------------
__device__ float g_xg_f[(size_t)T_LEN * 1024];
__device__ float g_xg_b[(size_t)T_LEN * 1024];
__device__ float g_h0[(size_t)T_LEN * 512];
__device__ float g_h1[(size_t)T_LEN * 512];

// ---------------- device helpers ----------------
__device__ __forceinline__ unsigned long long ffma2(unsigned long long a,
                                                    unsigned long long b,
                                                    unsigned long long c) {
    unsigned long long d;
    asm("fma.rn.f32x2 %0, %1, %2, %3;" : "=l"(d) : "l"(a), "l"(b), "l"(c));
    return d;
}
__device__ __forceinline__ uint32_t smaddr(const void* p) {
    return (uint32_t)__cvta_generic_to_shared(p);
}
__device__ __forceinline__ void mbar_init(uint32_t a, uint32_t cnt) {
    asm volatile("mbarrier.init.shared.b64 [%0], %1;" :: "r"(a), "r"(cnt) : "memory");
}
__device__ __forceinline__ void mbar_expect_tx(uint32_t a, uint32_t bytes) {
    asm volatile("mbarrier.arrive.expect_tx.shared.b64 _, [%0], %1;"
                 :: "r"(a), "r"(bytes) : "memory");
}
__device__ __forceinline__ uint32_t mapa_sh(uint32_t a, uint32_t rank) {
    uint32_t r;
    asm("mapa.shared::cluster.u32 %0, %1, %2;" : "=r"(r) : "r"(a), "r"(rank));
    return r;
}
__device__ __forceinline__ void mbar_wait_cl(uint32_t addr, uint32_t parity) {
    asm volatile(
        "{\n\t.reg .pred P;\n"
        "LW_%=:\n\t"
        "mbarrier.try_wait.parity.acquire.cluster.shared::cta.b64 P, [%0], %1;\n\t"
        "@P bra LD_%=;\n\t"
        "bra LW_%=;\n"
        "LD_%=:\n\t}"
        :: "r"(addr), "r"(parity) : "memory");
}
__device__ __forceinline__ void cluster_sync_() {
    asm volatile("barrier.cluster.arrive.aligned;" ::: "memory");
    asm volatile("barrier.cluster.wait.aligned;" ::: "memory");
}

// =================================================================================
// Kernel 1: layer-0 input projection. xg[t][row] = x[t] . w_ih[row] + b_ih + b_hh
// =================================================================================
__global__ void __launch_bounds__(256) xg0_kernel(
    const float* __restrict__ Y, const float* __restrict__ dT,
    const float* __restrict__ w_f, const float* __restrict__ bi_f, const float* __restrict__ bh_f,
    const float* __restrict__ w_b, const float* __restrict__ bi_b, const float* __restrict__ bh_b,
    float* __restrict__ out_f, float* __restrict__ out_b)
{
    __shared__ float xs[32][64];
    __shared__ float ws[64][128];
    const float* w  = blockIdx.z ? w_b  : w_f;
    const float* bi = blockIdx.z ? bi_b : bi_f;
    const float* bh = blockIdx.z ? bh_b : bh_f;
    float* out      = blockIdx.z ? out_b : out_f;

    const int tid = threadIdx.x;
    const int tbase = blockIdx.y * 32;
    const int cbase = blockIdx.x * 128;

    for (int i = tid; i < 32 * 64; i += 256) {
        int tt = i >> 6, k = i & 63;
        int t = tbase + tt;
        xs[tt][k] = (k < 63) ? Y[(size_t)t * 63 + k] : dT[t];
    }
    for (int i = tid; i < 128 * 64; i += 256) {
        int c = i >> 6, k = i & 63;
        ws[k][c] = w[(size_t)(cbase + c) * 64 + k];
    }
    __syncthreads();

    const int c = tid & 127;
    const int tr0 = tid >> 7;
    const float bias = bi[cbase + c] + bh[cbase + c];
    for (int tt = tr0; tt < 32; tt += 2) {
        float acc = bias;
        #pragma unroll
        for (int k = 0; k < 64; k++) acc += xs[tt][k] * ws[k][c];
        out[(size_t)(tbase + tt) * 1024 + cbase + c] = acc;
    }
}

// =================================================================================
// Kernel 2: LSTM scan v9 — R8 protocol + DUAL-CHUNK interleave (same direction,
// SHARED weight registers). 18 clusters of 8 CTAs: cluster cid = dir (cid&1),
// pair (cid>>1) handling chunks 2p and 2p+1 of that direction. Per pair-step:
// wait_A, wait_B (flights hidden by previous pair's compute) -> chain A compute/
// stage/bar/send -> chain B compute/stage/bar/send. Serial depth 3961 -> 2077
// with DSMEM flight off the critical path.
// =================================================================================
__global__ void __launch_bounds__(256, 1) lstm_scan_kernel(
    const float* __restrict__ xg_f, const float* __restrict__ xg_b,
    const float* __restrict__ whh_f, const float* __restrict__ whh_b,
    float* __restrict__ h_out)
{
    __shared__ __align__(16) unsigned char hA_raw[2 * HSTR];
    __shared__ __align__(16) unsigned char hB_raw[2 * HSTR];
    __shared__ __align__(16) float stgA[2][32];
    __shared__ __align__(16) float stgB[2][32];
    __shared__ unsigned long long mbar[4];   // [chain*2 + buf]

    const int tid  = threadIdx.x;
    const int lane = tid & 31;
    const int wid  = tid >> 5;
    const int rank = blockIdx.x & 7;
    const int cid  = blockIdx.x >> 3;        // 0..17
    const int dir  = cid & 1;
    const int pr   = cid >> 1;               // 0..8
    const float* xg  = dir ? xg_b  : xg_f;
    const float* whh = dir ? whh_b : whh_f;
    const int unit_base = rank * 32;

    // chunk parameters for chains A (2p) and B (2p+1)
    const int s0A = (2 * pr) * CHKL;
    const int lenA = (T_LEN - s0A < CHKL) ? (T_LEN - s0A) : CHKL;
    const int s0B = (2 * pr + 1) * CHKL;
    const int lenB = (T_LEN - s0B < CHKL) ? (T_LEN - s0B) : CHKL;

    int t0A, nsA, t0B, nsB;
    if (!dir) {
        int tw = s0A - WARM; if (tw < 0) tw = 0;
        t0A = tw; nsA = s0A + lenA - tw;
        tw = s0B - WARM; if (tw < 0) tw = 0;
        t0B = tw; nsB = s0B + lenB - tw;
    } else {
        int te = s0A + lenA - 1 + WARM; if (te > T_LEN - 1) te = T_LEN - 1;
        t0A = te; nsA = te - s0A + 1;
        te = s0B + lenB - 1 + WARM; if (te > T_LEN - 1) te = T_LEN - 1;
        t0B = te; nsB = te - s0B + 1;
    }
    const int wloA = s0A, whiA = s0A + lenA - 1;
    const int wloB = s0B, whiB = s0B + lenB - 1;

    const int q    = lane >> 1;      // pair 0..15
    const int half = lane & 1;
    const int gate = q >> 2;         // 0..3 (i,f,g,o)
    const int u    = q & 3;          // unit within warp
    const int ub4  = unit_base + 4 * wid;
    const int row  = gate * 256 + ub4 + u;

    // Load this thread's 128 weights (half row) — SHARED by both chains.
    unsigned long long w[64];
    {
        const ulonglong2* wg = (const ulonglong2*)(whh + (size_t)row * 256 + half * 128);
        #pragma unroll
        for (int i = 0; i < 32; i++) {
            ulonglong2 v = wg[i];
            w[2 * i] = v.x; w[2 * i + 1] = v.y;
        }
    }

    for (int i = tid; i < 2 * HSTR / 4; i += 256) {
        ((uint32_t*)hA_raw)[i] = 0u;
        ((uint32_t*)hB_raw)[i] = 0u;
    }
    if (tid < 4) mbar_init(smaddr(&mbar[tid]), 1);
    __syncthreads();
    const uint32_t hbA = smaddr(hA_raw);
    const uint32_t hbB = smaddr(hB_raw);
    const uint32_t mbb = smaddr(&mbar[0]);
    const uint32_t sA  = smaddr(&stgA[0][0]);
    const uint32_t sB  = smaddr(&stgB[0][0]);
    if (tid < 4) mbar_expect_tx(mbb + 8u * (uint32_t)tid, 1024u);  // pre-arm all
    __syncthreads();
    cluster_sync_();

    const uint32_t soff = (rank < 4) ? (uint32_t)(128 * rank)
                                     : (uint32_t)(528 + 128 * (rank - 4));
    uint32_t peer_hA = 0, peer_hB = 0, peer_mb = 0;
    if (lane == 0) {
        peer_hA = mapa_sh(hbA, (uint32_t)wid) + soff;
        peer_hB = mapa_sh(hbB, (uint32_t)wid) + soff;
        peer_mb = mapa_sh(mbb, (uint32_t)wid);
    }

    const uint32_t rdA = hbA + (half ? 528u : 0u);
    const uint32_t rdB = hbB + (half ? 528u : 0u);

    const int dt = dir ? -1 : 1;

    float cA = 0.f, cB = 0.f;   // cell states (lanes 0..3)
    float xgA = 0.f, xgAn = 0.f, xgB = 0.f, xgBn = 0.f;
    if (!half) {
        xgA = __ldg(&xg[(size_t)t0A * 1024 + row]);
        xgB = __ldg(&xg[(size_t)t0B * 1024 + row]);
    }
    int ph[4] = {0, 0, 0, 0};
    const int nmax = (nsA > nsB) ? nsA : nsB;

    for (int s = 0; s < nmax; s++) {
        const int buf = s & 1;
        const int nb  = buf ^ 1;

        // prefetch xg for step s+1 (loads land ~1 pair (~2000cyc) ahead of use)
        if (!half) {
            if (s + 1 < nsA) xgAn = __ldg(&xg[(size_t)(t0A + (s + 1) * dt) * 1024 + row]);
            if (s + 1 < nsB) xgBn = __ldg(&xg[(size_t)(t0B + (s + 1) * dt) * 1024 + row]);
        }

        if (s > 0) {
            if (s < nsA) {
                uint32_t mb = mbb + 8u * (uint32_t)buf;
                if (lane == 0) {
                    mbar_wait_cl(mb, (uint32_t)ph[buf]);
                    if (tid == 0) mbar_expect_tx(mb, 1024u);
                }
                __syncwarp();
                ph[buf] ^= 1;
            }
            if (s < nsB) {
                uint32_t mb = mbb + 8u * (uint32_t)(2 + buf);
                if (lane == 0) {
                    mbar_wait_cl(mb, (uint32_t)ph[2 + buf]);
                    if (tid == 0) mbar_expect_tx(mb, 1024u);
                }
                __syncwarp();
                ph[2 + buf] ^= 1;
            }
        }

        // ================= chain A =================
        if (s < nsA) {
            const uint32_t ra = rdA + (uint32_t)buf * (uint32_t)HSTR;
            unsigned long long a0 = 0ULL, a1 = 0ULL, a2 = 0ULL, a3 = 0ULL;
            #pragma unroll
            for (int i = 0; i < 8; i++) {
                ulonglong2 ha  = *(const ulonglong2*)(hA_raw + (ra - hbA) + 64u * i);
                ulonglong2 hb2 = *(const ulonglong2*)(hA_raw + (ra - hbA) + 64u * i + 16u);
                ulonglong2 hc  = *(const ulonglong2*)(hA_raw + (ra - hbA) + 64u * i + 32u);
                ulonglong2 hd  = *(const ulonglong2*)(hA_raw + (ra - hbA) + 64u * i + 48u);
                a0 = ffma2(w[8 * i + 0], ha.x,  a0);
                a1 = ffma2(w[8 * i + 1], ha.y,  a1);
                a2 = ffma2(w[8 * i + 2], hb2.x, a2);
                a3 = ffma2(w[8 * i + 3], hb2.y, a3);
                a0 = ffma2(w[8 * i + 4], hc.x,  a0);
                a1 = ffma2(w[8 * i + 5], hc.y,  a1);
                a2 = ffma2(w[8 * i + 6], hd.x,  a2);
                a3 = ffma2(w[8 * i + 7], hd.y,  a3);
            }
            float2 f0 = *(float2*)&a0, f1 = *(float2*)&a1;
            float2 f2 = *(float2*)&a2, f3 = *(float2*)&a3;
            float sum = ((f0.x + f0.y) + (f1.x + f1.y)) + ((f2.x + f2.y) + (f3.x + f3.y));
            sum += __shfl_xor_sync(0xffffffffu, sum, 1);
            if (!half) sum += xgA;

            const int uu = lane & 3;
            float iv = __shfl_sync(0xffffffffu, sum, 2 * uu);
            float fv = __shfl_sync(0xffffffffu, sum, 8 + 2 * uu);
            float gv = __shfl_sync(0xffffffffu, sum, 16 + 2 * uu);
            float ov = __shfl_sync(0xffffffffu, sum, 24 + 2 * uu);

            float ei = __expf(-iv), ef = __expf(-fv), eo = __expf(-ov);
            float eg = __expf(-2.f * fabsf(gv));
            float si = __fdividef(1.f, 1.f + ei);
            float sf = __fdividef(1.f, 1.f + ef);
            float so = __fdividef(1.f, 1.f + eo);
            float tg = copysignf(__fdividef(1.f - eg, 1.f + eg), gv);
            cA = sf * cA + si * tg;
            float ec = __expf(-2.f * fabsf(cA));
            float tc = copysignf(__fdividef(1.f - ec, 1.f + ec), cA);
            float h = so * tc;

            if (lane < 4) {
                stgA[buf][4 * wid + lane] = h;
                const int t = t0A + s * dt;
                if (t >= wloA && t <= whiA)
                    h_out[(size_t)t * 512 + dir * 256 + ub4 + lane] = h;
            }
        }
        __syncthreads();
        if (lane == 0 && (s + 1 < nsA)) {
            asm volatile("fence.proxy.async.shared::cta;" ::: "memory");
            asm volatile(
                "cp.async.bulk.shared::cluster.shared::cta.mbarrier::complete_tx::bytes "
                "[%0], [%1], %2, [%3];"
                :: "r"(peer_hA + (uint32_t)nb * (uint32_t)HSTR),
                   "r"(sA + (uint32_t)buf * 128u), "r"(128u),
                   "r"(peer_mb + 8u * (uint32_t)nb) : "memory");
        }

        // ================= chain B =================
        if (s < nsB) {
            const uint32_t ra = rdB + (uint32_t)buf * (uint32_t)HSTR;
            unsigned long long a0 = 0ULL, a1 = 0ULL, a2 = 0ULL, a3 = 0ULL;
            #pragma unroll
            for (int i = 0; i < 8; i++) {
                ulonglong2 ha  = *(const ulonglong2*)(hB_raw + (ra - hbB) + 64u * i);
                ulonglong2 hb2 = *(const ulonglong2*)(hB_raw + (ra - hbB) + 64u * i + 16u);
                ulonglong2 hc  = *(const ulonglong2*)(hB_raw + (ra - hbB) + 64u * i + 32u);
                ulonglong2 hd  = *(const ulonglong2*)(hB_raw + (ra - hbB) + 64u * i + 48u);
                a0 = ffma2(w[8 * i + 0], ha.x,  a0);
                a1 = ffma2(w[8 * i + 1], ha.y,  a1);
                a2 = ffma2(w[8 * i + 2], hb2.x, a2);
                a3 = ffma2(w[8 * i + 3], hb2.y, a3);
                a0 = ffma2(w[8 * i + 4], hc.x,  a0);
                a1 = ffma2(w[8 * i + 5], hc.y,  a1);
                a2 = ffma2(w[8 * i + 6], hd.x,  a2);
                a3 = ffma2(w[8 * i + 7], hd.y,  a3);
            }
            float2 f0 = *(float2*)&a0, f1 = *(float2*)&a1;
            float2 f2 = *(float2*)&a2, f3 = *(float2*)&a3;
            float sum = ((f0.x + f0.y) + (f1.x + f1.y)) + ((f2.x + f2.y) + (f3.x + f3.y));
            sum += __shfl_xor_sync(0xffffffffu, sum, 1);
            if (!half) sum += xgB;

            const int uu = lane & 3;
            float iv = __shfl_sync(0xffffffffu, sum, 2 * uu);
            float fv = __shfl_sync(0xffffffffu, sum, 8 + 2 * uu);
            float gv = __shfl_sync(0xffffffffu, sum, 16 + 2 * uu);
            float ov = __shfl_sync(0xffffffffu, sum, 24 + 2 * uu);

            float ei = __expf(-iv), ef = __expf(-fv), eo = __expf(-ov);
            float eg = __expf(-2.f * fabsf(gv));
            float si = __fdividef(1.f, 1.f + ei);
            float sf = __fdividef(1.f, 1.f + ef);
            float so = __fdividef(1.f, 1.f + eo);
            float tg = copysignf(__fdividef(1.f - eg, 1.f + eg), gv);
            cB = sf * cB + si * tg;
            float ec = __expf(-2.f * fabsf(cB));
            float tc = copysignf(__fdividef(1.f - ec, 1.f + ec), cB);
            float h = so * tc;

            if (lane < 4) {
                stgB[buf][4 * wid + lane] = h;
                const int t = t0B + s * dt;
                if (t >= wloB && t <= whiB)
                    h_out[(size_t)t * 512 + dir * 256 + ub4 + lane] = h;
            }
        }
        __syncthreads();
        if (lane == 0 && (s + 1 < nsB)) {
            asm volatile("fence.proxy.async.shared::cta;" ::: "memory");
            asm volatile(
                "cp.async.bulk.shared::cluster.shared::cta.mbarrier::complete_tx::bytes "
                "[%0], [%1], %2, [%3];"
                :: "r"(peer_hB + (uint32_t)nb * (uint32_t)HSTR),
                   "r"(sB + (uint32_t)buf * 128u), "r"(128u),
                   "r"(peer_mb + 8u * (uint32_t)(2 + nb)) : "memory");
        }

        xgA = xgAn;
        xgB = xgBn;
    }
    cluster_sync_();   // don't exit while peers' bulk writes may target our SMEM
}

// =================================================================================
// Kernel 3: layer-1 input projection GEMM v2 (PROVEN R15). BM=128, BN=64, BK=16.
// =================================================================================
#define ASTR 132
#define BSTR 68
__global__ void __launch_bounds__(256) xg1_gemm(
    const float* __restrict__ A,
    const float* __restrict__ Wf, const float* __restrict__ Wb,
    const float* __restrict__ bif, const float* __restrict__ bhf,
    const float* __restrict__ bib, const float* __restrict__ bhb,
    float* __restrict__ outf, float* __restrict__ outb)
{
    const float* W  = blockIdx.z ? Wb  : Wf;
    const float* bi = blockIdx.z ? bib : bif;
    const float* bh = blockIdx.z ? bhb : bhf;
    float* out      = blockIdx.z ? outb : outf;

    __shared__ __align__(16) float As[16][ASTR];
    __shared__ __align__(16) float Bs[16][BSTR];

    const int tid = threadIdx.x;
    const int bm = blockIdx.y * 128;
    const int bn = blockIdx.x * 64;
    const int tx = tid & 15;
    const int ty = tid >> 4;
    const int m0 = ty * 8;
    const int n0 = tx * 4;

    const int rowA0 = tid >> 2, kkA = tid & 3;
    const int rowA1 = (tid + 256) >> 2;
    const int rowW  = tid >> 2, kkW = tid & 3;

    float acc[8][4] = {};

    for (int k0 = 0; k0 < 512; k0 += 16) {
        float4 av0 = *(const float4*)&A[(size_t)(bm + rowA0) * 512 + k0 + kkA * 4];
        float4 av1 = *(const float4*)&A[(size_t)(bm + rowA1) * 512 + k0 + kkA * 4];
        float4 wv  = *(const float4*)&W[(size_t)(bn + rowW) * 512 + k0 + kkW * 4];
        __syncthreads();
        As[kkA * 4 + 0][rowA0] = av0.x; As[kkA * 4 + 1][rowA0] = av0.y;
        As[kkA * 4 + 2][rowA0] = av0.z; As[kkA * 4 + 3][rowA0] = av0.w;
        As[kkA * 4 + 0][rowA1] = av1.x; As[kkA * 4 + 1][rowA1] = av1.y;
        As[kkA * 4 + 2][rowA1] = av1.z; As[kkA * 4 + 3][rowA1] = av1.w;
        Bs[kkW * 4 + 0][rowW] = wv.x; Bs[kkW * 4 + 1][rowW] = wv.y;
        Bs[kkW * 4 + 2][rowW] = wv.z; Bs[kkW * 4 + 3][rowW] = wv.w;
        __syncthreads();
        #pragma unroll
        for (int k = 0; k < 16; k++) {
            float4 a0 = *(const float4*)&As[k][m0];
            float4 a1 = *(const float4*)&As[k][m0 + 4];
            float4 b  = *(const float4*)&Bs[k][n0];
            float a[8] = {a0.x, a0.y, a0.z, a0.w, a1.x, a1.y, a1.z, a1.w};
            float bb[4] = {b.x, b.y, b.z, b.w};
            #pragma unroll
            for (int i = 0; i < 8; i++)
                #pragma unroll
                for (int j = 0; j < 4; j++)
                    acc[i][j] += a[i] * bb[j];
        }
    }

    float bias[4];
    #pragma unroll
    for (int j = 0; j < 4; j++)
        bias[j] = bi[bn + n0 + j] + bh[bn + n0 + j];
    #pragma unroll
    for (int i = 0; i < 8; i++) {
        float4 o;
        o.x = acc[i][0] + bias[0];
        o.y = acc[i][1] + bias[1];
        o.z = acc[i][2] + bias[2];
        o.w = acc[i][3] + bias[3];
        *(float4*)&out[(size_t)(bm + m0 + i) * 1024 + bn + n0] = o;
    }
}

// =================================================================================
// Kernel 4: FC at inducing points + split output.
// =================================================================================
__global__ void __launch_bounds__(64) fc_gather_kernel(
    const float* __restrict__ h1, const int* __restrict__ idx,
    const float* __restrict__ fc, float* __restrict__ out)
{
    __shared__ float hrow[512];
    const int b = blockIdx.x;
    const int t = idx[b];
    const int tid = threadIdx.x;
    for (int i = tid; i < 512; i += 64) hrow[i] = h1[(size_t)t * 512 + i];
    __syncthreads();
    float acc = 0.f;
    #pragma unroll 8
    for (int k = 0; k < 512; k++) acc += hrow[k] * fc[(size_t)k * 64 + tid];
    if (tid < 32) out[b * 32 + tid] = acc;
    else          out[NI_ * OUT_ + b * 32 + (tid - 32)] = acc;
}

// =================================================================================
// Launch
// =================================================================================
extern "C" void kernel_launch(void* const* d_in, const int* in_sizes, int n_in,
                              void* d_out, int out_size) {
    const float* Y        = (const float*)d_in[0];
    const float* dT       = (const float*)d_in[1];
    const int*   induce   = (const int*)  d_in[2];
    const float* w_ih_l0f = (const float*)d_in[3];
    const float* w_hh_l0f = (const float*)d_in[4];
    const float* b_ih_l0f = (const float*)d_in[5];
    const float* b_hh_l0f = (const float*)d_in[6];
    const float* w_ih_l0b = (const float*)d_in[7];
    const float* w_hh_l0b = (const float*)d_in[8];
    const float* b_ih_l0b = (const float*)d_in[9];
    const float* b_hh_l0b = (const float*)d_in[10];
    const float* w_ih_l1f = (const float*)d_in[11];
    const float* w_hh_l1f = (const float*)d_in[12];
    const float* b_ih_l1f = (const float*)d_in[13];
    const float* b_hh_l1f = (const float*)d_in[14];
    const float* w_ih_l1b = (const float*)d_in[15];
    const float* w_hh_l1b = (const float*)d_in[16];
    const float* b_ih_l1b = (const float*)d_in[17];
    const float* b_hh_l1b = (const float*)d_in[18];
    const float* fc_w     = (const float*)d_in[19];
    float* out = (float*)d_out;

    float *xg_f, *xg_b, *h0, *h1;
    cudaGetSymbolAddress((void**)&xg_f, g_xg_f);
    cudaGetSymbolAddress((void**)&xg_b, g_xg_b);
    cudaGetSymbolAddress((void**)&h0, g_h0);
    cudaGetSymbolAddress((void**)&h1, g_h1);

    // 1) layer-0 gate preactivations
    xg0_kernel<<<dim3(8, T_LEN / 32, 2), 256>>>(
        Y, dT,
        w_ih_l0f, b_ih_l0f, b_hh_l0f,
        w_ih_l0b, b_ih_l0b, b_hh_l0b,
        xg_f, xg_b);

    // scan: 18 clusters of 8 CTAs (2 dirs x 9 pairs) = 144 CTAs
    cudaLaunchConfig_t cfg = {};
    cfg.gridDim  = dim3(8 * 2 * NPAIR, 1, 1);
    cfg.blockDim = dim3(256, 1, 1);
    cfg.dynamicSmemBytes = 0;
    cfg.stream = 0;
    cudaLaunchAttribute attr[1];
    attr[0].id = cudaLaunchAttributeClusterDimension;
    attr[0].val.clusterDim.x = 8;
    attr[0].val.clusterDim.y = 1;
    attr[0].val.clusterDim.z = 1;
    cfg.attrs = attr;
    cfg.numAttrs = 1;

    // 2) layer-0 scan
    cudaLaunchKernelEx(&cfg, lstm_scan_kernel,
                       (const float*)xg_f, (const float*)xg_b,
                       w_hh_l0f, w_hh_l0b, h0);

    // 3) layer-1 gate preactivations (reuse xg buffers)
    xg1_gemm<<<dim3(16, T_LEN / 128, 2), 256>>>(
        (const float*)h0,
        w_ih_l1f, w_ih_l1b,
        b_ih_l1f, b_hh_l1f, b_ih_l1b, b_hh_l1b,
        xg_f, xg_b);

    // 4) layer-1 scan
    cudaLaunchKernelEx(&cfg, lstm_scan_kernel,
                       (const float*)xg_f, (const float*)xg_b,
                       w_hh_l1f, w_hh_l1b, h1);

    // 5) FC + gather
    fc_gather_kernel<<<NI_, 64>>>((const float*)h1, induce, fc_w, out);
}